// round 4
// baseline (speedup 1.0000x reference)
#include <cuda_runtime.h>

#define NCLS    19
#define NBINS   15
#define HW      (512 * 1024)            // 2^19
#define NB      4
#define NPIX    (NB * HW)               // 2,097,152
#define NCELLS  (NCLS * NBINS)          // 285
#define NTHR    (NCLS * 32)             // 608: warp w owns class w
#define CHUNK   256                     // pixels per block-iteration
#define NCHUNKS (NPIX / CHUNK)          // 8192
#define GRID    296                     // 2 blocks / SM

// g_hist[c*15+b] = sum of 15*(p - [label==c]) over pixels with bin(p_c)=b.
// sce = sum(|g_hist|) / (15*C*N).  Invariant: zero at entry; last block resets.
__device__ float    g_hist[NCELLS];
__device__ unsigned g_count;

__global__ __launch_bounds__(NTHR, 2)
void ece_fused(const float* __restrict__ logits,
               const int*   __restrict__ labels,
               float*       __restrict__ out) {
    __shared__ float s_e[NCLS * CHUNK];      // exp values, [class][pixel]
    __shared__ float s_w[CHUNK];             // 15 / S per pixel
    __shared__ float s_hist[NCELLS];
    __shared__ bool  s_last;

    const int warp = threadIdx.x >> 5;       // = class id
    const int lane = threadIdx.x & 31;

    for (int i = threadIdx.x; i < NCELLS; i += NTHR) s_hist[i] = 0.f;

    // Cumulative bins: a0 = sum of t over t<=1, a1 over t<=2, a2 over t<=3.
    float a0 = 0.f, a1 = 0.f, a2 = 0.f;

    // Prologue load for software pipeline.
    unsigned ch = blockIdx.x;
    float4 x0, x1;
    {
        const unsigned base = ch * CHUNK;
        const float* p = logits + (size_t)(base >> 19) * (NCLS * HW)
                                + (size_t)warp * HW + (base & (HW - 1)) + 4 * lane;
        x0 = __ldg((const float4*)p);
        x1 = __ldg((const float4*)(p + CHUNK / 2));
    }
    __syncthreads();

    for (; ch < NCHUNKS; ch += GRID) {
        const unsigned base = ch * CHUNK;

        // Phase A: exp + stage to smem (each value exp'd exactly once).
        float4 e0, e1;
        e0.x = __expf(x0.x); e0.y = __expf(x0.y); e0.z = __expf(x0.z); e0.w = __expf(x0.w);
        e1.x = __expf(x1.x); e1.y = __expf(x1.y); e1.z = __expf(x1.z); e1.w = __expf(x1.w);
        ((float4*)(s_e + warp * CHUNK))[lane]      = e0;
        ((float4*)(s_e + warp * CHUNK))[32 + lane] = e1;

        // Prefetch next chunk (hides DRAM latency under phases B/C).
        const unsigned chn = ch + GRID;
        if (chn < NCHUNKS) {
            const unsigned nb = chn * CHUNK;
            const float* pn = logits + (size_t)(nb >> 19) * (NCLS * HW)
                                     + (size_t)warp * HW + (nb & (HW - 1)) + 4 * lane;
            x0 = __ldg((const float4*)pn);
            x1 = __ldg((const float4*)(pn + CHUNK / 2));
        }
        __syncthreads();

        // Phase B (warps 0-7): S per pixel, w = 15/S, and label correction.
        if (threadIdx.x < CHUNK) {
            const int pix = threadIdx.x;
            float S = 0.f;
#pragma unroll
            for (int c = 0; c < NCLS; c++) S += s_e[c * CHUNK + pix];
            const float wv = __fdividef(15.f, S);
            s_w[pix] = wv;
            const int lab = __ldg(labels + base + pix);
            const float tl = s_e[lab * CHUNK + pix] * wv;   // bank-conflict-free:
            const int bl = min(__float2int_ru(tl) - 1, NBINS - 1); // bank = pix%32
            atomicAdd(&s_hist[lab * NBINS + bl], -15.f);    // lab random -> spread
        }
        __syncthreads();

        // Phase C: each warp bins its own class values (label-free).
        const float4 w0 = ((const float4*)s_w)[lane];
        const float4 w1 = ((const float4*)s_w)[32 + lane];
#pragma unroll
        for (int j = 0; j < 8; j++) {
            const float ee = (j==0)?e0.x:(j==1)?e0.y:(j==2)?e0.z:(j==3)?e0.w
                           : (j==4)?e1.x:(j==5)?e1.y:(j==6)?e1.z:e1.w;
            const float ww = (j==0)?w0.x:(j==1)?w0.y:(j==2)?w0.z:(j==3)?w0.w
                           : (j==4)?w1.x:(j==5)?w1.y:(j==6)?w1.z:w1.w;
            const float t = ee * ww;                        // 15*p, always > 0
            if (t <= 1.f) a0 += t;
            if (t <= 2.f) a1 += t;
            if (t <= 3.f) a2 += t;
            if (t > 3.f) {                                  // ~3.3% of values
                const int bin = min(__float2int_ru(t) - 1, NBINS - 1);
                atomicAdd(&s_hist[warp * NBINS + bin], t);
            }
        }
        __syncthreads();   // protect s_e/s_w before next chunk's writes
    }

    // Warp-reduce the 3 scalars; lane 0 -> shared hist.
#pragma unroll
    for (int s = 16; s > 0; s >>= 1) {
        a0 += __shfl_xor_sync(~0u, a0, s);
        a1 += __shfl_xor_sync(~0u, a1, s);
        a2 += __shfl_xor_sync(~0u, a2, s);
    }
    if (lane == 0) {
        atomicAdd(&s_hist[warp * NBINS + 0], a0);
        atomicAdd(&s_hist[warp * NBINS + 1], a1 - a0);
        atomicAdd(&s_hist[warp * NBINS + 2], a2 - a1);
    }
    __syncthreads();

    for (int i = threadIdx.x; i < NCELLS; i += NTHR) {
        const float v = s_hist[i];
        if (v != 0.f) atomicAdd(&g_hist[i], v);
    }

    // Completion protocol; last block finalizes and restores invariants.
    __threadfence();
    __syncthreads();
    if (threadIdx.x == 0) {
        const unsigned r = atomicInc(&g_count, GRID - 1);   // wraps back to 0
        s_last = (r == GRID - 1);
    }
    __syncthreads();

    if (s_last && warp == 0) {
        __threadfence();
        double local = 0.0;
        for (int i = lane; i < NCELLS; i += 32) {
            local += fabs((double)g_hist[i]);
            g_hist[i] = 0.f;
        }
#pragma unroll
        for (int s = 16; s > 0; s >>= 1)
            local += __shfl_xor_sync(~0u, local, s);
        if (lane == 0)
            out[0] = (float)(local / (15.0 * (double)NCLS * (double)NPIX));
    }
}

extern "C" void kernel_launch(void* const* d_in, const int* in_sizes, int n_in,
                              void* d_out, int out_size) {
    const float* logits;
    const int*   labels;
    if (in_sizes[0] == NPIX) {               // defensive order detection by size
        labels = (const int*)d_in[0];
        logits = (const float*)d_in[1];
    } else {
        logits = (const float*)d_in[0];
        labels = (const int*)d_in[1];
    }
    float* out = (float*)d_out;

    ece_fused<<<GRID, NTHR>>>(logits, labels, out);
}

// round 5
// speedup vs baseline: 1.1683x; 1.1683x over previous
#include <cuda_runtime.h>

#define NCLS    19
#define NBINS   15
#define HW      (512 * 1024)          // 2^19
#define NPIX    (4 * HW)              // 2,097,152
#define NCELLS  (NCLS * NBINS)        // 285
#define NT      512
#define GRIDB   444                   // 3 blocks/SM on 148 SMs
#define PPB     (NT / 4)              // 128 pixels per block-iteration
#define STRIDE  (GRIDB * PPB)

// g_hist[c*15+b] = sum of 15*(p - [label==c]) over pixels with bin(p_c)=b.
// sce = sum(|g_hist|) / (15*C*N).  Invariant: zero at entry; last block resets.
__device__ float    g_hist[NCELLS];
__device__ unsigned g_count;

__global__ __launch_bounds__(NT, 3)
void ece_fused(const float* __restrict__ logits,
               const int*   __restrict__ labels,
               float*       __restrict__ out) {
    __shared__ float s_hist[NCELLS];
    __shared__ bool  s_last;
    for (int i = threadIdx.x; i < NCELLS; i += NT) s_hist[i] = 0.f;
    __syncthreads();

    const int g  = threadIdx.x & 3;       // class-group within the pixel quad
    const int q  = threadIdx.x >> 2;      // pixel slot within block
    const int c0 = g * 5;                 // first class of this group (g=3 has 4)

    // Cumulative register bins per owned class: a0 = sum v over t<=1, a1 over t<=2.
    float a0[5], a1[5];
#pragma unroll
    for (int i = 0; i < 5; i++) { a0[i] = 0.f; a1[i] = 0.f; }

    for (unsigned p = blockIdx.x * PPB + q; p < NPIX; p += STRIDE) {
        const unsigned b  = p >> 19;
        const unsigned hw = p & (HW - 1);
        const float* row  = logits + (size_t)b * (NCLS * HW) + hw;
        const int lab = __ldg(labels + p);          // broadcast within quad

        float e[5];
#pragma unroll
        for (int i = 0; i < 5; i++) {
            const int c = c0 + i;
            // dead slot (c==19) -> exp(-100)=0: contributes nothing anywhere
            e[i] = (c < NCLS) ? __ldg(row + (size_t)c * HW) : -100.f;
        }
        float S = 0.f;
#pragma unroll
        for (int i = 0; i < 5; i++) { e[i] = __expf(e[i]); S += e[i]; }
        // Softmax denominator across the 4-lane quad: two butterflies.
        S += __shfl_xor_sync(~0u, S, 1);
        S += __shfl_xor_sync(~0u, S, 2);
        const float w = __fdividef(15.f, S);

#pragma unroll
        for (int i = 0; i < 5; i++) {
            const float t = e[i] * w;               // 15*p  (0 for dead slot)
            float v = t;
            if (c0 + i == lab) v = t - 15.f;        // predicated label adjust
            if (t <= 1.f) a0[i] += v;               // cumulative levels
            if (t <= 2.f) a1[i] += v;
            if (t > 2.f) {                          // ~7.7%/value, spread cells
                const int bin = min(__float2int_ru(t) - 1, NBINS - 1);
                atomicAdd(&s_hist[(c0 + i) * NBINS + bin], v);
            }
        }
    }

    // Reduce accumulators over lanes of the same group (bits 2..4 of lane id).
    const int lane = threadIdx.x & 31;
#pragma unroll
    for (int i = 0; i < 5; i++) {
        float x0 = a0[i], x1 = a1[i];
#pragma unroll
        for (int s = 4; s < 32; s <<= 1) {
            x0 += __shfl_xor_sync(~0u, x0, s);
            x1 += __shfl_xor_sync(~0u, x1, s);
        }
        if (lane < 4 && c0 + i < NCLS) {            // lane == its own group id
            atomicAdd(&s_hist[(c0 + i) * NBINS + 0], x0);
            atomicAdd(&s_hist[(c0 + i) * NBINS + 1], x1 - x0);
        }
    }
    __syncthreads();

    for (int i = threadIdx.x; i < NCELLS; i += NT) {
        const float v = s_hist[i];
        if (v != 0.f) atomicAdd(&g_hist[i], v);
    }

    // Completion protocol; last block finalizes and restores invariants.
    __threadfence();
    __syncthreads();
    if (threadIdx.x == 0) {
        const unsigned r = atomicInc(&g_count, GRIDB - 1);   // wraps back to 0
        s_last = (r == GRIDB - 1);
    }
    __syncthreads();

    if (s_last && threadIdx.x < 32) {
        __threadfence();
        double local = 0.0;
        for (int i = lane; i < NCELLS; i += 32) {
            local += fabs((double)g_hist[i]);
            g_hist[i] = 0.f;
        }
#pragma unroll
        for (int s = 16; s > 0; s >>= 1)
            local += __shfl_xor_sync(~0u, local, s);
        if (lane == 0)
            out[0] = (float)(local / (15.0 * (double)NCLS * (double)NPIX));
    }
}

extern "C" void kernel_launch(void* const* d_in, const int* in_sizes, int n_in,
                              void* d_out, int out_size) {
    const float* logits;
    const int*   labels;
    if (in_sizes[0] == NPIX) {               // defensive order detection by size
        labels = (const int*)d_in[0];
        logits = (const float*)d_in[1];
    } else {
        logits = (const float*)d_in[0];
        labels = (const int*)d_in[1];
    }
    float* out = (float*)d_out;

    ece_fused<<<GRIDB, NT>>>(logits, labels, out);
}